// round 1
// baseline (speedup 1.0000x reference)
#include <cuda_runtime.h>
#include <math.h>

// ---------------- problem constants ----------------
#define B_TOT   256
#define N_TOK   343
#define C_DIM   384
#define H_HEADS 12
#define D_HEAD  32
#define NW      64
#define KV_DIM  768          // 2*C
#define M_ROWS  (B_TOT * N_TOK)   // 87808 = 686 * 128

#define KROW    36           // padded row stride for k/v smem tiles (float4-aligned)

// ---------------- scratch (device globals: allowed) ----------------
__device__ float g_kv[(size_t)B_TOT * N_TOK * KV_DIM];  // kv projection output
__device__ float g_x [(size_t)B_TOT * N_TOK * C_DIM];   // attention output (pre-proj)

// =====================================================================
// SGEMM: C[M,N] = A[M,K] (+A2) @ B[K,N] + bias[N]
// BM=BN=128, BK=16, 256 threads, 8x8 per thread.
// =====================================================================
template<bool FUSE_ADD>
__global__ __launch_bounds__(256)
void sgemm128(const float* __restrict__ A, const float* __restrict__ A2,
              const float* __restrict__ B, const float* __restrict__ bias,
              float* __restrict__ C, int M, int Nn, int K)
{
    __shared__ float As[16][128];
    __shared__ float Bs[16][128];

    const int tid = threadIdx.x;
    const int tx  = tid & 15;        // col group
    const int ty  = tid >> 4;        // row group
    const int bx  = blockIdx.x;      // col block
    const int by  = blockIdx.y;      // row block

    // A tile loaders: 128 rows x 16 cols -> 2 float4 per thread
    const int aRow = tid >> 2;            // 0..63
    const int aCol = (tid & 3) * 4;       // 0,4,8,12
    // B tile loaders: 16 rows x 128 cols -> 2 float4 per thread
    const int bRow = tid >> 5;            // 0..7
    const int bCol = (tid & 31) * 4;      // 0..124

    const float* Aptr  = A  + (size_t)(by * 128) * K;
    const float* A2ptr = FUSE_ADD ? (A2 + (size_t)(by * 128) * K) : nullptr;
    const float* Bptr  = B + bx * 128;

    float acc[8][8];
    #pragma unroll
    for (int i = 0; i < 8; i++)
        #pragma unroll
        for (int j = 0; j < 8; j++) acc[i][j] = 0.f;

    for (int k0 = 0; k0 < K; k0 += 16) {
        #pragma unroll
        for (int i = 0; i < 2; i++) {
            int r = aRow + i * 64;
            float4 av = *(const float4*)(Aptr + (size_t)r * K + k0 + aCol);
            if (FUSE_ADD) {
                float4 a2 = *(const float4*)(A2ptr + (size_t)r * K + k0 + aCol);
                av.x += a2.x; av.y += a2.y; av.z += a2.z; av.w += a2.w;
            }
            As[aCol + 0][r] = av.x;
            As[aCol + 1][r] = av.y;
            As[aCol + 2][r] = av.z;
            As[aCol + 3][r] = av.w;
        }
        #pragma unroll
        for (int i = 0; i < 2; i++) {
            int r = bRow + i * 8;
            *(float4*)&Bs[r][bCol] = *(const float4*)(Bptr + (size_t)(k0 + r) * Nn + bCol);
        }
        __syncthreads();

        #pragma unroll
        for (int kk = 0; kk < 16; kk++) {
            float ra[8], rb[8];
            *(float4*)&ra[0] = *(const float4*)&As[kk][ty * 8];
            *(float4*)&ra[4] = *(const float4*)&As[kk][ty * 8 + 4];
            *(float4*)&rb[0] = *(const float4*)&Bs[kk][tx * 8];
            *(float4*)&rb[4] = *(const float4*)&Bs[kk][tx * 8 + 4];
            #pragma unroll
            for (int i = 0; i < 8; i++)
                #pragma unroll
                for (int j = 0; j < 8; j++)
                    acc[i][j] += ra[i] * rb[j];
        }
        __syncthreads();
    }

    const int cCol = bx * 128 + tx * 8;
    float bv[8];
    #pragma unroll
    for (int j = 0; j < 8; j++) bv[j] = bias[cCol + j];

    #pragma unroll
    for (int i = 0; i < 8; i++) {
        size_t r = (size_t)(by * 128 + ty * 8 + i);
        float4 o0 = make_float4(acc[i][0] + bv[0], acc[i][1] + bv[1],
                                acc[i][2] + bv[2], acc[i][3] + bv[3]);
        float4 o1 = make_float4(acc[i][4] + bv[4], acc[i][5] + bv[5],
                                acc[i][6] + bv[6], acc[i][7] + bv[7]);
        *(float4*)(C + r * Nn + cCol)     = o0;
        *(float4*)(C + r * Nn + cCol + 4) = o1;
    }
}

// =====================================================================
// Fused cosine-attention kernel.
// grid = (H, B), block = 384 threads (one thread per query row, 343 active).
// smem: normalized K tile [343][36], V tile [343][36], bias table [409+pad],
//       positional encodings e[343].
// attn(n,m) = (qn . kn) * exp(min(ls_h, ln100)) + rpb[e(n)-e(m)+204, h] + mask[b%64, n, m]
// online softmax + PV accumulation in registers, then write [b, n, h*32+d].
// =====================================================================
#define ATTN_SMEM_FLOATS (N_TOK * KROW * 2 + 412)
#define ATTN_SMEM_BYTES  (ATTN_SMEM_FLOATS * 4 + N_TOK * 4)

__global__ __launch_bounds__(384)
void attn_kernel(const float* __restrict__ kv, const float* __restrict__ x_up,
                 const float* __restrict__ mask, const float* __restrict__ rpb,
                 const float* __restrict__ logit_scale, float* __restrict__ xout)
{
    extern __shared__ float sm[];
    float* ks     = sm;                         // [343][36]
    float* vs     = sm + N_TOK * KROW;          // [343][36]
    float* bias_t = vs + N_TOK * KROW;          // [409] (+3 pad)
    int*   e_enc  = (int*)(bias_t + 412);       // [343]

    const int h   = blockIdx.x;
    const int b   = blockIdx.y;
    const int tid = threadIdx.x;

    // ---- cooperative loads ----
    const float* kvb = kv + (size_t)b * N_TOK * KV_DIM + h * D_HEAD;
    for (int i = tid; i < N_TOK * 8; i += 384) {
        int row = i >> 3, d4 = (i & 7) * 4;
        float4 k4 = *(const float4*)(kvb + (size_t)row * KV_DIM + d4);
        float4 v4 = *(const float4*)(kvb + (size_t)row * KV_DIM + 384 + d4);
        *(float4*)&ks[row * KROW + d4] = k4;
        *(float4*)&vs[row * KROW + d4] = v4;
    }
    for (int i = tid; i < 409; i += 384) bias_t[i] = rpb[i * H_HEADS + h];
    if (tid < N_TOK) {
        int s = tid / 49, r = tid % 49;
        e_enc[tid] = 20 * s + 13 * (r / 7) + (r % 7);
    }
    __syncthreads();

    // ---- normalize K rows (one thread per row) ----
    if (tid < N_TOK) {
        float* kr = &ks[tid * KROW];
        float ssq = 0.f;
        #pragma unroll
        for (int d = 0; d < 32; d++) ssq += kr[d] * kr[d];
        float inv = 1.0f / fmaxf(sqrtf(ssq), 1e-12f);
        #pragma unroll
        for (int d = 0; d < 32; d++) kr[d] *= inv;
    }
    __syncthreads();

    if (tid >= N_TOK) return;
    const int n = tid;

    // ---- q load + normalize, fold logit scale in ----
    float q[32];
    const float* qp = x_up + ((size_t)b * N_TOK + n) * C_DIM + h * D_HEAD;
    float ssq = 0.f;
    #pragma unroll
    for (int d4 = 0; d4 < 8; d4++) {
        float4 v4 = *(const float4*)(qp + d4 * 4);
        q[d4*4+0] = v4.x; q[d4*4+1] = v4.y; q[d4*4+2] = v4.z; q[d4*4+3] = v4.w;
        ssq += v4.x*v4.x + v4.y*v4.y + v4.z*v4.z + v4.w*v4.w;
    }
    float qinv = 1.0f / fmaxf(sqrtf(ssq), 1e-12f);
    float scale = __expf(fminf(logit_scale[h], 4.6051702f));  // ln(100)
    float qs = qinv * scale;
    #pragma unroll
    for (int d = 0; d < 32; d++) q[d] *= qs;

    const float* mrow = mask + ((size_t)(b & (NW - 1)) * N_TOK + n) * N_TOK;
    const int en = e_enc[n] + 204;

    // ---- online softmax over all keys ----
    float o[32];
    #pragma unroll
    for (int d = 0; d < 32; d++) o[d] = 0.f;
    float mrun = -1e30f, l = 0.f;

    for (int m = 0; m < N_TOK; m++) {
        const float* kr = &ks[m * KROW];
        float dot = 0.f;
        #pragma unroll
        for (int d4 = 0; d4 < 8; d4++) {
            float4 k4 = *(const float4*)(kr + d4 * 4);
            dot += q[d4*4+0]*k4.x + q[d4*4+1]*k4.y + q[d4*4+2]*k4.z + q[d4*4+3]*k4.w;
        }
        float s = dot + bias_t[en - e_enc[m]] + mrow[m];

        if (s > mrun) {
            float c = __expf(mrun - s);   // 0 on first iteration (mrun=-1e30)
            l *= c;
            #pragma unroll
            for (int d = 0; d < 32; d++) o[d] *= c;
            mrun = s;
        }
        float p = __expf(s - mrun);
        l += p;
        const float* vr = &vs[m * KROW];
        #pragma unroll
        for (int d4 = 0; d4 < 8; d4++) {
            float4 v4 = *(const float4*)(vr + d4 * 4);
            o[d4*4+0] += p * v4.x;
            o[d4*4+1] += p * v4.y;
            o[d4*4+2] += p * v4.z;
            o[d4*4+3] += p * v4.w;
        }
    }

    float invl = 1.0f / l;
    float* outp = xout + ((size_t)b * N_TOK + n) * C_DIM + h * D_HEAD;
    #pragma unroll
    for (int d4 = 0; d4 < 8; d4++) {
        float4 v4 = make_float4(o[d4*4+0]*invl, o[d4*4+1]*invl,
                                o[d4*4+2]*invl, o[d4*4+3]*invl);
        *(float4*)(outp + d4 * 4) = v4;
    }
}

// =====================================================================
// launch
// =====================================================================
extern "C" void kernel_launch(void* const* d_in, const int* in_sizes, int n_in,
                              void* d_out, int out_size)
{
    const float* skip   = (const float*)d_in[0];
    const float* x_up   = (const float*)d_in[1];
    const float* pos    = (const float*)d_in[2];
    const float* mask   = (const float*)d_in[3];
    const float* kv_w   = (const float*)d_in[4];
    const float* kv_b   = (const float*)d_in[5];
    const float* proj_w = (const float*)d_in[6];
    const float* proj_b = (const float*)d_in[7];
    const float* lsc    = (const float*)d_in[8];
    const float* rpb    = (const float*)d_in[9];
    float* out = (float*)d_out;

    float *kvp, *xp;
    cudaGetSymbolAddress((void**)&kvp, g_kv);
    cudaGetSymbolAddress((void**)&xp,  g_x);

    cudaFuncSetAttribute(attn_kernel, cudaFuncAttributeMaxDynamicSharedMemorySize,
                         ATTN_SMEM_BYTES);

    // 1) kv projection: [87808,384] @ [384,768] + bias
    sgemm128<false><<<dim3(KV_DIM / 128, M_ROWS / 128), 256>>>(
        skip, nullptr, kv_w, kv_b, kvp, M_ROWS, KV_DIM, C_DIM);

    // 2) fused cosine window attention
    attn_kernel<<<dim3(H_HEADS, B_TOT), 384, ATTN_SMEM_BYTES>>>(
        kvp, x_up, mask, rpb, lsc, xp);

    // 3) output projection with fused (+pos_embed): [87808,384] @ [384,384] + bias
    sgemm128<true><<<dim3(C_DIM / 128, M_ROWS / 128), 256>>>(
        xp, pos, proj_w, proj_b, out, M_ROWS, C_DIM, C_DIM);
}

// round 4
// speedup vs baseline: 1.2179x; 1.2179x over previous
#include <cuda_runtime.h>
#include <math.h>
#include <cstdint>

// ---------------- problem constants ----------------
#define B_TOT   256
#define N_TOK   343
#define C_DIM   384
#define H_HEADS 12
#define D_HEAD  32
#define NW      64
#define KV_DIM  768          // 2*C
#define M_ROWS  (B_TOT * N_TOK)   // 87808 = 686 * 128

#define KROW    36           // padded row stride for k/v smem tiles in attention

// ---------------- scratch (device globals: allowed) ----------------
__device__ float g_kv[(size_t)B_TOT * N_TOK * KV_DIM];  // kv projection output
__device__ float g_x [(size_t)B_TOT * N_TOK * C_DIM];   // attention output (pre-proj)

// ---------------- helpers ----------------
__device__ __forceinline__ float to_tf32(float x) {
    uint32_t u;
    asm("cvt.rna.tf32.f32 %0, %1;" : "=r"(u) : "f"(x));
    return __uint_as_float(u);
}

// D += A(16x8) * B(8x8), tf32 operands, fp32 accum. Standard documented layout.
__device__ __forceinline__ void mma16n8k8(float* d, const uint32_t* a, const uint32_t* b) {
    asm volatile(
        "mma.sync.aligned.m16n8k8.row.col.f32.tf32.tf32.f32 "
        "{%0,%1,%2,%3}, {%4,%5,%6,%7}, {%8,%9}, {%0,%1,%2,%3};"
        : "+f"(d[0]), "+f"(d[1]), "+f"(d[2]), "+f"(d[3])
        : "r"(a[0]), "r"(a[1]), "r"(a[2]), "r"(a[3]), "r"(b[0]), "r"(b[1]));
}

// =====================================================================
// Tensor-core GEMM via mma.sync (tf32):
//   C[M,Nn] = (A (+A2)) @ B + bias      A:[M,K] row-major, B:[K,Nn] row-major
// CTA tile 128x128, BK=16, 8 warps (4 M x 2 N), warp tile 32x64.
// =====================================================================
#define SM_STRIDE 136   // floats; makes fragment LDS conflict-free

template<bool FUSE_ADD>
__global__ __launch_bounds__(256, 2)
void tmma_gemm(const float* __restrict__ A, const float* __restrict__ A2,
               const float* __restrict__ B, const float* __restrict__ bias,
               float* __restrict__ C, int Nn, int K)
{
    __shared__ float As[16][SM_STRIDE];   // As[k][m]
    __shared__ float Bs[16][SM_STRIDE];   // Bs[k][n]

    const int tid  = threadIdx.x;
    const int lane = tid & 31;
    const int wid  = tid >> 5;
    const int bx = blockIdx.x, by = blockIdx.y;
    const int tg = lane & 3;        // threadID_in_group
    const int g  = lane >> 2;       // groupID
    const int wm = (wid & 3) * 32;  // warp row offset in tile
    const int wn = (wid >> 2) * 64; // warp col offset in tile

    // gmem loader indices
    const int arow = tid >> 1;            // 0..127
    const int akg  = (tid & 1) * 8;       // 0 / 8
    const int brow = tid >> 4;            // 0..15
    const int bcol = (tid & 15) * 8;      // 0..120

    const float* Ap  = A + (size_t)(by * 128 + arow) * K + akg;
    const float* A2p = FUSE_ADD ? (A2 + (size_t)(by * 128 + arow) * K + akg) : nullptr;
    const float* Bp  = B + (size_t)brow * Nn + bx * 128 + bcol;

    float d[2][8][4];
    #pragma unroll
    for (int mt = 0; mt < 2; mt++)
        #pragma unroll
        for (int nt = 0; nt < 8; nt++)
            #pragma unroll
            for (int r = 0; r < 4; r++) d[mt][nt][r] = 0.f;

    // prefetch k-tile 0
    float ar[8], br[8];
    {
        float4 a0 = *(const float4*)(Ap);
        float4 a1 = *(const float4*)(Ap + 4);
        if (FUSE_ADD) {
            float4 p0 = *(const float4*)(A2p);
            float4 p1 = *(const float4*)(A2p + 4);
            a0.x += p0.x; a0.y += p0.y; a0.z += p0.z; a0.w += p0.w;
            a1.x += p1.x; a1.y += p1.y; a1.z += p1.z; a1.w += p1.w;
        }
        ar[0]=a0.x; ar[1]=a0.y; ar[2]=a0.z; ar[3]=a0.w;
        ar[4]=a1.x; ar[5]=a1.y; ar[6]=a1.z; ar[7]=a1.w;
        float4 b0 = *(const float4*)(Bp);
        float4 b1 = *(const float4*)(Bp + 4);
        br[0]=b0.x; br[1]=b0.y; br[2]=b0.z; br[3]=b0.w;
        br[4]=b1.x; br[5]=b1.y; br[6]=b1.z; br[7]=b1.w;
    }

    const int NT = K / 16;
    for (int kt = 0; kt < NT; kt++) {
        __syncthreads();
        #pragma unroll
        for (int j = 0; j < 8; j++) As[akg + j][arow] = to_tf32(ar[j]);
        {
            float4 o0 = make_float4(to_tf32(br[0]), to_tf32(br[1]), to_tf32(br[2]), to_tf32(br[3]));
            float4 o1 = make_float4(to_tf32(br[4]), to_tf32(br[5]), to_tf32(br[6]), to_tf32(br[7]));
            *(float4*)&Bs[brow][bcol]     = o0;
            *(float4*)&Bs[brow][bcol + 4] = o1;
        }
        __syncthreads();

        if (kt + 1 < NT) {
            Ap += 16; if (FUSE_ADD) A2p += 16;
            Bp += (size_t)16 * Nn;
            float4 a0 = *(const float4*)(Ap);
            float4 a1 = *(const float4*)(Ap + 4);
            if (FUSE_ADD) {
                float4 p0 = *(const float4*)(A2p);
                float4 p1 = *(const float4*)(A2p + 4);
                a0.x += p0.x; a0.y += p0.y; a0.z += p0.z; a0.w += p0.w;
                a1.x += p1.x; a1.y += p1.y; a1.z += p1.z; a1.w += p1.w;
            }
            ar[0]=a0.x; ar[1]=a0.y; ar[2]=a0.z; ar[3]=a0.w;
            ar[4]=a1.x; ar[5]=a1.y; ar[6]=a1.z; ar[7]=a1.w;
            float4 b0 = *(const float4*)(Bp);
            float4 b1 = *(const float4*)(Bp + 4);
            br[0]=b0.x; br[1]=b0.y; br[2]=b0.z; br[3]=b0.w;
            br[4]=b1.x; br[5]=b1.y; br[6]=b1.z; br[7]=b1.w;
        }

        const uint32_t* uAs = (const uint32_t*)&As[0][0];
        const uint32_t* uBs = (const uint32_t*)&Bs[0][0];
        #pragma unroll
        for (int ks = 0; ks < 2; ks++) {
            const int k = ks * 8;
            uint32_t afr[2][4], bfr[8][2];
            #pragma unroll
            for (int mt = 0; mt < 2; mt++) {
                const int m = wm + mt * 16;
                afr[mt][0] = uAs[(k + tg)     * SM_STRIDE + m + g];
                afr[mt][1] = uAs[(k + tg)     * SM_STRIDE + m + g + 8];
                afr[mt][2] = uAs[(k + tg + 4) * SM_STRIDE + m + g];
                afr[mt][3] = uAs[(k + tg + 4) * SM_STRIDE + m + g + 8];
            }
            #pragma unroll
            for (int nt = 0; nt < 8; nt++) {
                const int n = wn + nt * 8;
                bfr[nt][0] = uBs[(k + tg)     * SM_STRIDE + n + g];
                bfr[nt][1] = uBs[(k + tg + 4) * SM_STRIDE + n + g];
            }
            #pragma unroll
            for (int mt = 0; mt < 2; mt++)
                #pragma unroll
                for (int nt = 0; nt < 8; nt++)
                    mma16n8k8(d[mt][nt], afr[mt], bfr[nt]);
        }
    }

    // epilogue: d0,d1 -> (row, 2tg..2tg+1); d2,d3 -> (row+8, ...)
    #pragma unroll
    for (int mt = 0; mt < 2; mt++) {
        const int r0 = by * 128 + wm + mt * 16 + g;
        #pragma unroll
        for (int nt = 0; nt < 8; nt++) {
            const int c = bx * 128 + wn + nt * 8 + 2 * tg;
            const float b0 = bias[c], b1 = bias[c + 1];
            float2 lo = make_float2(d[mt][nt][0] + b0, d[mt][nt][1] + b1);
            float2 hi = make_float2(d[mt][nt][2] + b0, d[mt][nt][3] + b1);
            *(float2*)(C + (size_t)r0 * Nn + c)        = lo;
            *(float2*)(C + (size_t)(r0 + 8) * Nn + c)  = hi;
        }
    }
}

// =====================================================================
// Fused cosine-attention kernel (unchanged from R1 — passed at 1.8e-7).
// =====================================================================
#define ATTN_SMEM_FLOATS (N_TOK * KROW * 2 + 412)
#define ATTN_SMEM_BYTES  (ATTN_SMEM_FLOATS * 4 + N_TOK * 4)

__global__ __launch_bounds__(384)
void attn_kernel(const float* __restrict__ kv, const float* __restrict__ x_up,
                 const float* __restrict__ mask, const float* __restrict__ rpb,
                 const float* __restrict__ logit_scale, float* __restrict__ xout)
{
    extern __shared__ float sm[];
    float* ks     = sm;
    float* vs     = sm + N_TOK * KROW;
    float* bias_t = vs + N_TOK * KROW;
    int*   e_enc  = (int*)(bias_t + 412);

    const int h   = blockIdx.x;
    const int b   = blockIdx.y;
    const int tid = threadIdx.x;

    const float* kvb = kv + (size_t)b * N_TOK * KV_DIM + h * D_HEAD;
    for (int i = tid; i < N_TOK * 8; i += 384) {
        int row = i >> 3, d4 = (i & 7) * 4;
        float4 k4 = *(const float4*)(kvb + (size_t)row * KV_DIM + d4);
        float4 v4 = *(const float4*)(kvb + (size_t)row * KV_DIM + 384 + d4);
        *(float4*)&ks[row * KROW + d4] = k4;
        *(float4*)&vs[row * KROW + d4] = v4;
    }
    for (int i = tid; i < 409; i += 384) bias_t[i] = rpb[i * H_HEADS + h];
    if (tid < N_TOK) {
        int s = tid / 49, r = tid % 49;
        e_enc[tid] = 20 * s + 13 * (r / 7) + (r % 7);
    }
    __syncthreads();

    if (tid < N_TOK) {
        float* kr = &ks[tid * KROW];
        float ssq = 0.f;
        #pragma unroll
        for (int d = 0; d < 32; d++) ssq += kr[d] * kr[d];
        float inv = 1.0f / fmaxf(sqrtf(ssq), 1e-12f);
        #pragma unroll
        for (int d = 0; d < 32; d++) kr[d] *= inv;
    }
    __syncthreads();

    if (tid >= N_TOK) return;
    const int n = tid;

    float q[32];
    const float* qp = x_up + ((size_t)b * N_TOK + n) * C_DIM + h * D_HEAD;
    float ssq = 0.f;
    #pragma unroll
    for (int d4 = 0; d4 < 8; d4++) {
        float4 v4 = *(const float4*)(qp + d4 * 4);
        q[d4*4+0] = v4.x; q[d4*4+1] = v4.y; q[d4*4+2] = v4.z; q[d4*4+3] = v4.w;
        ssq += v4.x*v4.x + v4.y*v4.y + v4.z*v4.z + v4.w*v4.w;
    }
    float qinv = 1.0f / fmaxf(sqrtf(ssq), 1e-12f);
    float scale = __expf(fminf(logit_scale[h], 4.6051702f));
    float qs = qinv * scale;
    #pragma unroll
    for (int d = 0; d < 32; d++) q[d] *= qs;

    const float* mrow = mask + ((size_t)(b & (NW - 1)) * N_TOK + n) * N_TOK;
    const int en = e_enc[n] + 204;

    float o[32];
    #pragma unroll
    for (int d = 0; d < 32; d++) o[d] = 0.f;
    float mrun = -1e30f, l = 0.f;

    for (int m = 0; m < N_TOK; m++) {
        const float* kr = &ks[m * KROW];
        float dot = 0.f;
        #pragma unroll
        for (int d4 = 0; d4 < 8; d4++) {
            float4 k4 = *(const float4*)(kr + d4 * 4);
            dot += q[d4*4+0]*k4.x + q[d4*4+1]*k4.y + q[d4*4+2]*k4.z + q[d4*4+3]*k4.w;
        }
        float s = dot + bias_t[en - e_enc[m]] + mrow[m];

        if (s > mrun) {
            float c = __expf(mrun - s);
            l *= c;
            #pragma unroll
            for (int d = 0; d < 32; d++) o[d] *= c;
            mrun = s;
        }
        float p = __expf(s - mrun);
        l += p;
        const float* vr = &vs[m * KROW];
        #pragma unroll
        for (int d4 = 0; d4 < 8; d4++) {
            float4 v4 = *(const float4*)(vr + d4 * 4);
            o[d4*4+0] += p * v4.x;
            o[d4*4+1] += p * v4.y;
            o[d4*4+2] += p * v4.z;
            o[d4*4+3] += p * v4.w;
        }
    }

    float invl = 1.0f / l;
    float* outp = xout + ((size_t)b * N_TOK + n) * C_DIM + h * D_HEAD;
    #pragma unroll
    for (int d4 = 0; d4 < 8; d4++) {
        float4 v4 = make_float4(o[d4*4+0]*invl, o[d4*4+1]*invl,
                                o[d4*4+2]*invl, o[d4*4+3]*invl);
        *(float4*)(outp + d4 * 4) = v4;
    }
}

// =====================================================================
// launch
// =====================================================================
extern "C" void kernel_launch(void* const* d_in, const int* in_sizes, int n_in,
                              void* d_out, int out_size)
{
    const float* skip   = (const float*)d_in[0];
    const float* x_up   = (const float*)d_in[1];
    const float* pos    = (const float*)d_in[2];
    const float* mask   = (const float*)d_in[3];
    const float* kv_w   = (const float*)d_in[4];
    const float* kv_b   = (const float*)d_in[5];
    const float* proj_w = (const float*)d_in[6];
    const float* proj_b = (const float*)d_in[7];
    const float* lsc    = (const float*)d_in[8];
    const float* rpb    = (const float*)d_in[9];
    float* out = (float*)d_out;

    float *kvp, *xp;
    cudaGetSymbolAddress((void**)&kvp, g_kv);
    cudaGetSymbolAddress((void**)&xp,  g_x);

    cudaFuncSetAttribute(attn_kernel, cudaFuncAttributeMaxDynamicSharedMemorySize,
                         ATTN_SMEM_BYTES);

    // 1) kv projection (mma.sync tf32): [87808,384] @ [384,768] + bias
    tmma_gemm<false><<<dim3(KV_DIM / 128, M_ROWS / 128), 256>>>(
        skip, nullptr, kv_w, kv_b, kvp, KV_DIM, C_DIM);

    // 2) fused cosine window attention (fp32)
    attn_kernel<<<dim3(H_HEADS, B_TOT), 384, ATTN_SMEM_BYTES>>>(
        kvp, x_up, mask, rpb, lsc, xp);

    // 3) output projection (mma.sync tf32, fused +pos_embed): [87808,384] @ [384,384] + bias
    tmma_gemm<true><<<dim3(C_DIM / 128, M_ROWS / 128), 256>>>(
        xp, pos, proj_w, proj_b, out, C_DIM, C_DIM);
}